// round 7
// baseline (speedup 1.0000x reference)
#include <cuda_runtime.h>
#include <cstdint>

#define Ndim  2048
#define NN    (Ndim * Ndim)
#define NFLAT (Ndim * (Ndim - 1) / 2)
#define BATCHN 8192

// Taylor coefficients 1/i!
#define C0 1.0f
#define C1 1.0f
#define C2 0.5f
#define C3 1.6666666666666666e-1f
#define C4 4.1666666666666664e-2f
#define C5 8.3333333333333332e-3f
#define C6 1.3888888888888889e-3f
#define C7 1.9841269841269841e-4f
#define C8 2.4801587301587302e-5f
#define C9 2.7557319223985893e-6f

// Scratch (allocation-free rule: __device__ globals)
__device__ float g_S [NN];
__device__ float g_S2[NN];
__device__ float g_W [NN];
__device__ float g_A [NN];
__device__ float g_B [NN];

// Build antisymmetric S from strict-upper-triangle flat vector (jnp.triu_indices order).
__global__ void build_S(const float* __restrict__ Sf, float* __restrict__ S) {
    int idx = blockIdx.x * blockDim.x + threadIdx.x;
    if (idx >= NN) return;
    int r = idx >> 11;
    int c = idx & (Ndim - 1);
    float v = 0.0f;
    if (r < c)      v =  Sf[r * (2 * Ndim - r - 1) / 2 + (c - r - 1)];
    else if (r > c) v = -Sf[c * (2 * Ndim - c - 1) / 2 + (r - c - 1)];
    S[idx] = v;
}

// R1 = C6*I + C7*S + C8*S2 + C9*W   (top Paterson-Stockmeyer block, no matmul)
__global__ void lincomb_R1(const float* __restrict__ S, const float* __restrict__ S2,
                           const float* __restrict__ W, float* __restrict__ R) {
    int idx = blockIdx.x * blockDim.x + threadIdx.x;
    if (idx >= NN) return;
    int r = idx >> 11;
    int c = idx & (Ndim - 1);
    float v = C7 * S[idx] + C8 * S2[idx] + C9 * W[idx];
    if (r == c) v += C6;
    R[idx] = v;
}

// ---------------------------------------------------------------------------
// FP32 SIMT GEMM:  C = A(MxK) @ B(KxN)  + eI*I + e1*E1 + e2*E2   (E1/E2 nullable)
// 128x128 tile, BK=8, 256 threads, 8x8 per-thread microtile, double-buffered smem.
// All problem dims are multiples of 128/8 -> no bounds checks in mainloop.
// ---------------------------------------------------------------------------
#define BM 128
#define BN 128
#define BK 8
#define TM 8
#define TN 8

__global__ __launch_bounds__(256)
void sgemm_epi(const float* __restrict__ A, const float* __restrict__ B,
               float* __restrict__ C, int M, int Nc, int K,
               float eI, const float* __restrict__ E1, float e1,
               const float* __restrict__ E2, float e2)
{
    __shared__ float As[2][BK][BM + 4];   // +4 pad kills STS bank conflicts
    __shared__ float Bs[2][BK][BN];

    const int tid = threadIdx.x;
    const int tx = tid & 15;       // 16 thread-cols
    const int ty = tid >> 4;       // 16 thread-rows

    // Global-load assignment: one float4 per thread per tile for A and B each.
    const int aRow = tid >> 1;             // 0..127
    const int aCol = (tid & 1) << 2;       // 0 or 4
    const int bRow = tid >> 5;             // 0..7
    const int bCol = (tid & 31) << 2;      // 0..124

    const float* Aptr = A + (size_t)(blockIdx.y * BM + aRow) * K + aCol;
    const float* Bptr = B + (size_t)bRow * Nc + blockIdx.x * BN + bCol;

    // Preload tile 0
    float4 a4 = *(const float4*)Aptr;
    float4 b4 = *(const float4*)Bptr;
    As[0][aCol + 0][aRow] = a4.x;
    As[0][aCol + 1][aRow] = a4.y;
    As[0][aCol + 2][aRow] = a4.z;
    As[0][aCol + 3][aRow] = a4.w;
    *(float4*)&Bs[0][bRow][bCol] = b4;
    __syncthreads();

    float acc[TM][TN];
#pragma unroll
    for (int i = 0; i < TM; i++)
#pragma unroll
        for (int j = 0; j < TN; j++) acc[i][j] = 0.0f;

    const int nt = K / BK;
    int buf = 0;
    for (int kt = 0; kt < nt; kt++) {
        float4 na, nb;
        if (kt + 1 < nt) {
            na = *(const float4*)(Aptr + (kt + 1) * BK);
            nb = *(const float4*)(Bptr + (size_t)(kt + 1) * BK * Nc);
        }
#pragma unroll
        for (int k = 0; k < BK; k++) {
            float a[TM], b[TN];
            *(float4*)&a[0] = *(const float4*)&As[buf][k][ty * TM];
            *(float4*)&a[4] = *(const float4*)&As[buf][k][ty * TM + 4];
            *(float4*)&b[0] = *(const float4*)&Bs[buf][k][tx * TN];
            *(float4*)&b[4] = *(const float4*)&Bs[buf][k][tx * TN + 4];
#pragma unroll
            for (int i = 0; i < TM; i++)
#pragma unroll
                for (int j = 0; j < TN; j++)
                    acc[i][j] += a[i] * b[j];
        }
        if (kt + 1 < nt) {
            buf ^= 1;
            As[buf][aCol + 0][aRow] = na.x;
            As[buf][aCol + 1][aRow] = na.y;
            As[buf][aCol + 2][aRow] = na.z;
            As[buf][aCol + 3][aRow] = na.w;
            *(float4*)&Bs[buf][bRow][bCol] = nb;
        }
        __syncthreads();
    }

    // Epilogue: C = acc + eI*I + e1*E1 + e2*E2
    const int rowBase = blockIdx.y * BM + ty * TM;
    const int colBase = blockIdx.x * BN + tx * TN;
#pragma unroll
    for (int i = 0; i < TM; i++) {
        const int r = rowBase + i;
        const size_t off = (size_t)r * Nc + colBase;
        float v[TN];
#pragma unroll
        for (int j = 0; j < TN; j++) v[j] = acc[i][j];
        if (E1) {
            float4 p = *(const float4*)(E1 + off);
            float4 q = *(const float4*)(E1 + off + 4);
            v[0] += e1 * p.x; v[1] += e1 * p.y; v[2] += e1 * p.z; v[3] += e1 * p.w;
            v[4] += e1 * q.x; v[5] += e1 * q.y; v[6] += e1 * q.z; v[7] += e1 * q.w;
        }
        if (E2) {
            float4 p = *(const float4*)(E2 + off);
            float4 q = *(const float4*)(E2 + off + 4);
            v[0] += e2 * p.x; v[1] += e2 * p.y; v[2] += e2 * p.z; v[3] += e2 * p.w;
            v[4] += e2 * q.x; v[5] += e2 * q.y; v[6] += e2 * q.z; v[7] += e2 * q.w;
        }
        if (eI != 0.0f) {
            int d = r - colBase;
            if (d >= 0 && d < TN) v[d] += eI;
        }
        *(float4*)(C + off)     = make_float4(v[0], v[1], v[2], v[3]);
        *(float4*)(C + off + 4) = make_float4(v[4], v[5], v[6], v[7]);
    }
}

extern "C" void kernel_launch(void* const* d_in, const int* in_sizes, int n_in,
                              void* d_out, int out_size) {
    // Identify inputs by size (X: BATCH*N, S_flat: N*(N-1)/2)
    const float* X;
    const float* Sf;
    if (in_sizes[0] == NFLAT) { Sf = (const float*)d_in[0]; X = (const float*)d_in[1]; }
    else                      { X  = (const float*)d_in[0]; Sf = (const float*)d_in[1]; }
    float* Y = (float*)d_out;

    float *S, *S2, *W, *Ab, *Bb;
    cudaGetSymbolAddress((void**)&S,  g_S);
    cudaGetSymbolAddress((void**)&S2, g_S2);
    cudaGetSymbolAddress((void**)&W,  g_W);
    cudaGetSymbolAddress((void**)&Ab, g_A);
    cudaGetSymbolAddress((void**)&Bb, g_B);

    build_S<<<NN / 256, 256>>>(Sf, S);

    dim3 gSq(Ndim / BN, Ndim / BM);   // 16 x 16
    // S2 = S @ S
    sgemm_epi<<<gSq, 256>>>(S, S, S2, Ndim, Ndim, Ndim, 0.f, nullptr, 0.f, nullptr, 0.f);
    // W = S2 @ S  (= S^3)
    sgemm_epi<<<gSq, 256>>>(S2, S, W, Ndim, Ndim, Ndim, 0.f, nullptr, 0.f, nullptr, 0.f);
    // Ab = R1 = C6 I + C7 S + C8 S2 + C9 W
    lincomb_R1<<<NN / 256, 256>>>(S, S2, W, Ab);
    // Bb = R2 = W @ R1 + C3 I + C4 S + C5 S2
    sgemm_epi<<<gSq, 256>>>(W, Ab, Bb, Ndim, Ndim, Ndim, C3, S, C4, S2, C5);
    // Ab = Q  = W @ R2 + C0 I + C1 S + C2 S2
    sgemm_epi<<<gSq, 256>>>(W, Bb, Ab, Ndim, Ndim, Ndim, C0, S, C1, S2, C2);
    // Y = X @ Q
    dim3 gY(Ndim / BN, BATCHN / BM);  // 16 x 64
    sgemm_epi<<<gY, 256>>>(X, Ab, Y, BATCHN, Ndim, Ndim, 0.f, nullptr, 0.f, nullptr, 0.f);
}

// round 10
// speedup vs baseline: 3.8047x; 3.8047x over previous
#include <cuda_runtime.h>
#include <cuda_bf16.h>
#include <cstdint>

#define Ndim  2048
#define NN    (Ndim * Ndim)
#define NFLAT (Ndim * (Ndim - 1) / 2)
#define BATCHN 8192

// Taylor coefficients 1/i!
#define C0 1.0f
#define C1 1.0f
#define C2 0.5f
#define C3 1.6666666666666666e-1f
#define C4 4.1666666666666664e-2f
#define C5 8.3333333333333332e-3f
#define C6 1.3888888888888889e-3f
#define C7 1.9841269841269841e-4f
#define C8 2.4801587301587302e-5f
#define C9 2.7557319223985893e-6f

// ---------------- scratch (__device__ globals; allocation-free rule) -------
__device__ float g_S [NN];
__device__ float g_S2[NN];
__device__ float g_W [NN];

__device__ __nv_bfloat16 g_Shi [NN], g_Slo [NN];
__device__ __nv_bfloat16 g_Snhi[NN], g_Snlo[NN];     // -S splits (Bt of S)
__device__ __nv_bfloat16 g_S2hi[NN], g_S2lo[NN];
__device__ __nv_bfloat16 g_Whi [NN], g_Wlo [NN];
__device__ __nv_bfloat16 g_R1thi[NN], g_R1tlo[NN];
__device__ __nv_bfloat16 g_R2thi[NN], g_R2tlo[NN];
__device__ __nv_bfloat16 g_Qthi [NN], g_Qtlo [NN];
__device__ __nv_bfloat16 g_Xhi[BATCHN * Ndim], g_Xlo[BATCHN * Ndim];

// ---------------------- PTX helpers (base-target legal only) ---------------
__device__ __forceinline__ uint32_t smem_to_u32(const void* p) {
    uint32_t a;
    asm("{ .reg .u64 t; cvta.to.shared.u64 t, %1; cvt.u32.u64 %0, t; }"
        : "=r"(a) : "l"(p));
    return a;
}
__device__ __forceinline__ void cp16(uint32_t s, const void* g) {
    asm volatile("cp.async.cg.shared.global [%0], [%1], 16;" :: "r"(s), "l"(g));
}
#define CP_COMMIT() asm volatile("cp.async.commit_group;" ::: "memory")
#define CP_WAIT(n)  asm volatile("cp.async.wait_group %0;" :: "n"(n) : "memory")

__device__ __forceinline__ void ldm_x4(uint32_t* r, uint32_t addr) {
    asm volatile("ldmatrix.sync.aligned.m8n8.x4.shared.b16 {%0,%1,%2,%3}, [%4];"
                 : "=r"(r[0]), "=r"(r[1]), "=r"(r[2]), "=r"(r[3]) : "r"(addr));
}
__device__ __forceinline__ void mma16816(float* c, const uint32_t* a,
                                         uint32_t b0, uint32_t b1) {
    asm volatile(
        "mma.sync.aligned.m16n8k16.row.col.f32.bf16.bf16.f32 "
        "{%0,%1,%2,%3}, {%4,%5,%6,%7}, {%8,%9}, {%0,%1,%2,%3};"
        : "+f"(c[0]), "+f"(c[1]), "+f"(c[2]), "+f"(c[3])
        : "r"(a[0]), "r"(a[1]), "r"(a[2]), "r"(a[3]), "r"(b0), "r"(b1));
}

// ---------------------- preprocessing kernels ------------------------------
__global__ void build_S(const float* __restrict__ Sf, float* __restrict__ S) {
    int idx = blockIdx.x * blockDim.x + threadIdx.x;
    if (idx >= NN) return;
    int r = idx >> 11;
    int c = idx & (Ndim - 1);
    float v = 0.0f;
    if (r < c)      v =  Sf[r * (2 * Ndim - r - 1) / 2 + (c - r - 1)];
    else if (r > c) v = -Sf[c * (2 * Ndim - c - 1) / 2 + (r - c - 1)];
    S[idx] = v;
}

__global__ void split_S4(const float* __restrict__ src,
                         __nv_bfloat16* __restrict__ hi, __nv_bfloat16* __restrict__ lo,
                         __nv_bfloat16* __restrict__ nhi, __nv_bfloat16* __restrict__ nlo) {
    int i = blockIdx.x * blockDim.x + threadIdx.x;
    if (i >= NN) return;
    float x = src[i];
    __nv_bfloat16 h = __float2bfloat16(x);
    float l = x - __bfloat162float(h);
    __nv_bfloat16 lb = __float2bfloat16(l);
    hi[i] = h; lo[i] = lb;
    nhi[i] = __hneg(h); nlo[i] = __hneg(lb);
}

__global__ void split_plain(const float* __restrict__ src,
                            __nv_bfloat16* __restrict__ hi, __nv_bfloat16* __restrict__ lo,
                            int n) {
    int i = blockIdx.x * blockDim.x + threadIdx.x;
    if (i >= n) return;
    float x = src[i];
    __nv_bfloat16 h = __float2bfloat16(x);
    hi[i] = h;
    lo[i] = __float2bfloat16(x - __bfloat162float(h));
}

// R1^T = C6*I - C7*S + C8*S2 - C9*W  -> split directly to bf16 hi/lo
__global__ void lincomb_R1t_split(const float* __restrict__ S, const float* __restrict__ S2,
                                  const float* __restrict__ W,
                                  __nv_bfloat16* __restrict__ hi, __nv_bfloat16* __restrict__ lo) {
    int idx = blockIdx.x * blockDim.x + threadIdx.x;
    if (idx >= NN) return;
    int r = idx >> 11;
    int c = idx & (Ndim - 1);
    float v = -C7 * S[idx] + C8 * S2[idx] - C9 * W[idx];
    if (r == c) v += C6;
    __nv_bfloat16 h = __float2bfloat16(v);
    hi[idx] = h;
    lo[idx] = __float2bfloat16(v - __bfloat162float(h));
}

// ---------------------------------------------------------------------------
// HMMA split-bf16 GEMM (base-target legal: mma.sync + ldmatrix + cp.async):
//   D[M,Nc] (fp32) = (Ahi+Alo)[M,K] @ ((Bthi+Btlo)[Nc,K])^T   (hh + hl + lh)
//   + eI*I + e1*E1 + e2*E2 (fp32, nullable)
//   outputs: Cf (fp32, nullable) and/or (Ho,Lo2) bf16 split pair (nullable)
// CTA tile 128x128, BK=32, 3-stage cp.async pipeline, 256 threads (8 warps,
// warp tile 64x32). Smem rows padded 32->40 bf16 for conflict-free ldmatrix.
// ---------------------------------------------------------------------------
#define BKC     32
#define STAGES  3
#define TPAD    40
#define TROWB   (TPAD * 2)            // 80 bytes per padded row
#define TILE_B  (128 * TROWB)         // 10240 bytes per tile
#define STAGE_B (4 * TILE_B)          // 40960 bytes (Ahi,Alo,Bhi,Blo)
#define SMEM_B  (STAGES * STAGE_B)    // 122880 bytes

__global__ __launch_bounds__(256)
void mma_gemm(const __nv_bfloat16* __restrict__ Ahi, const __nv_bfloat16* __restrict__ Alo,
              const __nv_bfloat16* __restrict__ Bthi, const __nv_bfloat16* __restrict__ Btlo,
              float* __restrict__ Cf,
              __nv_bfloat16* __restrict__ Ho, __nv_bfloat16* __restrict__ Lo2,
              const float* __restrict__ E1, float e1,
              const float* __restrict__ E2, float e2, float eI,
              int M, int Nc, int K)
{
    extern __shared__ __align__(128) char sm[];
    const uint32_t smu = smem_to_u32(sm);

    const int tid  = threadIdx.x;
    const int lane = tid & 31;
    const int wid  = tid >> 5;
    const int wrow = wid & 1;          // 2 warp-rows of 64
    const int wcol = wid >> 1;         // 4 warp-cols of 32
    const int rl   = lane & 7;
    const int gq   = lane >> 3;

    const int rowA = blockIdx.y * 128;
    const int rowB = blockIdx.x * 128;

    // per-lane ldmatrix byte offsets within a tile
    const int aoff = (wrow * 64 + rl + (gq & 1) * 8) * TROWB + (gq >> 1) * 16;
    const int boff = (wcol * 32 + rl + (gq >> 1) * 8) * TROWB + (gq & 1) * 16;

    // gmem load assignment: 512 16B-chunks per tile, 2 per thread
    const int ldrow0 = tid >> 2;              // chunk0 row (0..63)
    const int lds0   = tid & 3;               // 16B slot in row
    const int ldrow1 = (tid + 256) >> 2;      // chunk1 row (64..127)

    float acc[64];
#pragma unroll
    for (int i = 0; i < 64; i++) acc[i] = 0.0f;

    const int nt = K / BKC;

    // ---- issue one chunk's 4 tiles via cp.async --------------------------
    auto issue = [&](int kt, int stage) {
        const int kc = kt * BKC;
        const uint32_t sb = smu + stage * STAGE_B;
        const uint32_t so0 = ldrow0 * TROWB + lds0 * 16;
        const uint32_t so1 = ldrow1 * TROWB + lds0 * 16;
        const size_t ga0 = (size_t)(rowA + ldrow0) * K + kc + lds0 * 8;
        const size_t ga1 = (size_t)(rowA + ldrow1) * K + kc + lds0 * 8;
        const size_t gb0 = (size_t)(rowB + ldrow0) * K + kc + lds0 * 8;
        const size_t gb1 = (size_t)(rowB + ldrow1) * K + kc + lds0 * 8;
        cp16(sb + so0,              Ahi  + ga0);
        cp16(sb + so1,              Ahi  + ga1);
        cp16(sb + TILE_B + so0,     Alo  + ga0);
        cp16(sb + TILE_B + so1,     Alo  + ga1);
        cp16(sb + 2 * TILE_B + so0, Bthi + gb0);
        cp16(sb + 2 * TILE_B + so1, Bthi + gb1);
        cp16(sb + 3 * TILE_B + so0, Btlo + gb0);
        cp16(sb + 3 * TILE_B + so1, Btlo + gb1);
    };

    // prologue: stages 0 and 1
    issue(0, 0); CP_COMMIT();
    issue(1, 1); CP_COMMIT();

    int stage = 0;
    for (int kt = 0; kt < nt; kt++) {
        CP_WAIT(1);
        __syncthreads();

        if (kt + 2 < nt) issue(kt + 2, (stage + 2) % STAGES);
        CP_COMMIT();   // commit every iter (possibly empty) to keep counts uniform

        const uint32_t sb = smu + stage * STAGE_B;
#pragma unroll
        for (int ks = 0; ks < 2; ks++) {
            const int kb = ks * 32;
            uint32_t ah[16], al[16], bh[8], bl[8];
#pragma unroll
            for (int mt = 0; mt < 4; mt++)
                ldm_x4(ah + mt * 4, sb + aoff + mt * 16 * TROWB + kb);
#pragma unroll
            for (int ng = 0; ng < 2; ng++)
                ldm_x4(bh + ng * 4, sb + 2 * TILE_B + boff + ng * 16 * TROWB + kb);
#pragma unroll
            for (int ng = 0; ng < 2; ng++)
                ldm_x4(bl + ng * 4, sb + 3 * TILE_B + boff + ng * 16 * TROWB + kb);
#pragma unroll
            for (int mt = 0; mt < 4; mt++)
                ldm_x4(al + mt * 4, sb + TILE_B + aoff + mt * 16 * TROWB + kb);

#pragma unroll
            for (int mt = 0; mt < 4; mt++) {
#pragma unroll
                for (int n8 = 0; n8 < 4; n8++) {
                    float* c = acc + (mt * 4 + n8) * 4;
                    const int bi = (n8 >> 1) * 4 + (n8 & 1) * 2;
                    mma16816(c, ah + mt * 4, bh[bi], bh[bi + 1]);   // hi*hi
                    mma16816(c, ah + mt * 4, bl[bi], bl[bi + 1]);   // hi*lo
                    mma16816(c, al + mt * 4, bh[bi], bh[bi + 1]);   // lo*hi
                }
            }
        }
        __syncthreads();
        stage = (stage + 1) % STAGES;
    }

    // ---------------- epilogue --------------------------------------------
    const int rbase = rowA + wrow * 64 + (lane >> 2);
    const int cbase = rowB + wcol * 32 + (lane & 3) * 2;

#pragma unroll
    for (int mt = 0; mt < 4; mt++) {
#pragma unroll
        for (int n8 = 0; n8 < 4; n8++) {
            const float* c = acc + (mt * 4 + n8) * 4;
            const int col = cbase + n8 * 8;
#pragma unroll
            for (int h = 0; h < 2; h++) {
                const int r = rbase + mt * 16 + h * 8;
                float v0 = c[h * 2], v1 = c[h * 2 + 1];
                const size_t off = (size_t)r * Nc + col;
                if (E1) {
                    float2 e = *reinterpret_cast<const float2*>(E1 + off);
                    v0 += e1 * e.x; v1 += e1 * e.y;
                }
                if (E2) {
                    float2 e = *reinterpret_cast<const float2*>(E2 + off);
                    v0 += e2 * e.x; v1 += e2 * e.y;
                }
                if (eI != 0.0f) {
                    if (r == col)     v0 += eI;
                    if (r == col + 1) v1 += eI;
                }
                if (Cf)
                    *reinterpret_cast<float2*>(Cf + off) = make_float2(v0, v1);
                if (Ho) {
                    __nv_bfloat16 h0 = __float2bfloat16(v0);
                    __nv_bfloat16 h1 = __float2bfloat16(v1);
                    __nv_bfloat16 l0 = __float2bfloat16(v0 - __bfloat162float(h0));
                    __nv_bfloat16 l1 = __float2bfloat16(v1 - __bfloat162float(h1));
                    uint32_t hp = (uint32_t)__bfloat16_as_ushort(h0) |
                                  ((uint32_t)__bfloat16_as_ushort(h1) << 16);
                    uint32_t lp = (uint32_t)__bfloat16_as_ushort(l0) |
                                  ((uint32_t)__bfloat16_as_ushort(l1) << 16);
                    *reinterpret_cast<uint32_t*>(Ho  + off) = hp;
                    *reinterpret_cast<uint32_t*>(Lo2 + off) = lp;
                }
            }
        }
    }
}

// ---------------------------------------------------------------------------
extern "C" void kernel_launch(void* const* d_in, const int* in_sizes, int n_in,
                              void* d_out, int out_size) {
    const float* X;
    const float* Sf;
    if (in_sizes[0] == NFLAT) { Sf = (const float*)d_in[0]; X = (const float*)d_in[1]; }
    else                      { X  = (const float*)d_in[0]; Sf = (const float*)d_in[1]; }
    float* Y = (float*)d_out;

    float *S, *S2, *W;
    __nv_bfloat16 *Shi, *Slo, *Snhi, *Snlo, *S2hi, *S2lo, *Whi, *Wlo;
    __nv_bfloat16 *R1thi, *R1tlo, *R2thi, *R2tlo, *Qthi, *Qtlo, *Xhi, *Xlo;
    cudaGetSymbolAddress((void**)&S,   g_S);
    cudaGetSymbolAddress((void**)&S2,  g_S2);
    cudaGetSymbolAddress((void**)&W,   g_W);
    cudaGetSymbolAddress((void**)&Shi,  g_Shi);  cudaGetSymbolAddress((void**)&Slo,  g_Slo);
    cudaGetSymbolAddress((void**)&Snhi, g_Snhi); cudaGetSymbolAddress((void**)&Snlo, g_Snlo);
    cudaGetSymbolAddress((void**)&S2hi, g_S2hi); cudaGetSymbolAddress((void**)&S2lo, g_S2lo);
    cudaGetSymbolAddress((void**)&Whi,  g_Whi);  cudaGetSymbolAddress((void**)&Wlo,  g_Wlo);
    cudaGetSymbolAddress((void**)&R1thi, g_R1thi); cudaGetSymbolAddress((void**)&R1tlo, g_R1tlo);
    cudaGetSymbolAddress((void**)&R2thi, g_R2thi); cudaGetSymbolAddress((void**)&R2tlo, g_R2tlo);
    cudaGetSymbolAddress((void**)&Qthi,  g_Qthi);  cudaGetSymbolAddress((void**)&Qtlo,  g_Qtlo);
    cudaGetSymbolAddress((void**)&Xhi,  g_Xhi);  cudaGetSymbolAddress((void**)&Xlo,  g_Xlo);

    cudaFuncSetAttribute(mma_gemm, cudaFuncAttributeMaxDynamicSharedMemorySize, SMEM_B);

    build_S<<<NN / 256, 256>>>(Sf, S);
    split_S4<<<NN / 256, 256>>>(S, Shi, Slo, Snhi, Snlo);
    split_plain<<<(BATCHN * Ndim) / 256, 256>>>(X, Xhi, Xlo, BATCHN * Ndim);

    dim3 gSq(Ndim / 128, Ndim / 128);   // 16 x 16

    // S2 = S @ S      (Bt = -S  =>  D = S @ (-S)^T = S@S). out: fp32 + splits
    mma_gemm<<<gSq, 256, SMEM_B>>>(Shi, Slo, Snhi, Snlo,
                                   S2, S2hi, S2lo,
                                   nullptr, 0.f, nullptr, 0.f, 0.f,
                                   Ndim, Ndim, Ndim);
    // W = S2 @ S      out: fp32 + splits
    mma_gemm<<<gSq, 256, SMEM_B>>>(S2hi, S2lo, Snhi, Snlo,
                                   W, Whi, Wlo,
                                   nullptr, 0.f, nullptr, 0.f, 0.f,
                                   Ndim, Ndim, Ndim);
    // R1^T = C6 I - C7 S + C8 S2 - C9 W  (elementwise, split directly)
    lincomb_R1t_split<<<NN / 256, 256>>>(S, S2, W, R1thi, R1tlo);

    // R2^T = R1^T @ (-W) + C3 I - C4 S + C5 S2   (Bt = W since (-W)^T = W)
    mma_gemm<<<gSq, 256, SMEM_B>>>(R1thi, R1tlo, Whi, Wlo,
                                   nullptr, R2thi, R2tlo,
                                   S, -C4, S2, C5, C3,
                                   Ndim, Ndim, Ndim);
    // Q^T  = R2^T @ (-W) + C0 I - C1 S + C2 S2
    mma_gemm<<<gSq, 256, SMEM_B>>>(R2thi, R2tlo, Whi, Wlo,
                                   nullptr, Qthi, Qtlo,
                                   S, -C1, S2, C2, C0,
                                   Ndim, Ndim, Ndim);
    // Y = X @ Q       (Bt = Q^T row-major = Qt). out: fp32 -> d_out
    dim3 gY(Ndim / 128, BATCHN / 128);  // 16 x 64
    mma_gemm<<<gY, 256, SMEM_B>>>(Xhi, Xlo, Qthi, Qtlo,
                                  Y, nullptr, nullptr,
                                  nullptr, 0.f, nullptr, 0.f, 0.f,
                                  BATCHN, Ndim, Ndim);
}

// round 11
// speedup vs baseline: 4.7170x; 1.2398x over previous
#include <cuda_runtime.h>
#include <cuda_bf16.h>
#include <cstdint>

#define Ndim  2048
#define NN    (Ndim * Ndim)
#define NFLAT (Ndim * (Ndim - 1) / 2)
#define BATCHN 8192

// Taylor coefficients 1/i!
#define C0 1.0f
#define C1 1.0f
#define C2 0.5f
#define C3 1.6666666666666666e-1f
#define C4 4.1666666666666664e-2f
#define C5 8.3333333333333332e-3f
#define C6 1.3888888888888889e-3f
#define C7 1.9841269841269841e-4f
#define C8 2.4801587301587302e-5f
#define C9 2.7557319223985893e-6f

// ---------------- scratch (__device__ globals; allocation-free rule) -------
__device__ float g_S [NN];
__device__ float g_S2[NN];
__device__ float g_W [NN];

__device__ __nv_bfloat16 g_Shi [NN], g_Slo [NN];
__device__ __nv_bfloat16 g_Snhi[NN], g_Snlo[NN];     // -S splits (Bt of S)
__device__ __nv_bfloat16 g_S2hi[NN], g_S2lo[NN];
__device__ __nv_bfloat16 g_Whi [NN], g_Wlo [NN];
__device__ __nv_bfloat16 g_R1thi[NN], g_R1tlo[NN];
__device__ __nv_bfloat16 g_R2thi[NN], g_R2tlo[NN];
__device__ __nv_bfloat16 g_Qthi [NN], g_Qtlo [NN];
__device__ __nv_bfloat16 g_Xhi[BATCHN * Ndim], g_Xlo[BATCHN * Ndim];

// ---------------------- PTX helpers (base-target legal only) ---------------
__device__ __forceinline__ uint32_t smem_to_u32(const void* p) {
    uint32_t a;
    asm("{ .reg .u64 t; cvta.to.shared.u64 t, %1; cvt.u32.u64 %0, t; }"
        : "=r"(a) : "l"(p));
    return a;
}
__device__ __forceinline__ void cp16(uint32_t s, const void* g) {
    asm volatile("cp.async.cg.shared.global [%0], [%1], 16;" :: "r"(s), "l"(g));
}
#define CP_COMMIT() asm volatile("cp.async.commit_group;" ::: "memory")
#define CP_WAIT(n)  asm volatile("cp.async.wait_group %0;" :: "n"(n) : "memory")

__device__ __forceinline__ void ldm_x4(uint32_t* r, uint32_t addr) {
    asm volatile("ldmatrix.sync.aligned.m8n8.x4.shared.b16 {%0,%1,%2,%3}, [%4];"
                 : "=r"(r[0]), "=r"(r[1]), "=r"(r[2]), "=r"(r[3]) : "r"(addr));
}
__device__ __forceinline__ void mma16816(float* c, const uint32_t* a,
                                         uint32_t b0, uint32_t b1) {
    asm volatile(
        "mma.sync.aligned.m16n8k16.row.col.f32.bf16.bf16.f32 "
        "{%0,%1,%2,%3}, {%4,%5,%6,%7}, {%8,%9}, {%0,%1,%2,%3};"
        : "+f"(c[0]), "+f"(c[1]), "+f"(c[2]), "+f"(c[3])
        : "r"(a[0]), "r"(a[1]), "r"(a[2]), "r"(a[3]), "r"(b0), "r"(b1));
}

// swizzled byte offset inside one 128x32-bf16 tile (rows of 64B, 4 x 16B chunks)
__device__ __forceinline__ uint32_t swz(int row, int chunk) {
    return (uint32_t)(row * 64 + ((chunk ^ ((row >> 1) & 3)) << 4));
}

// ---------------------- preprocessing kernels ------------------------------
// Build antisymmetric S and its bf16 splits (+ negated splits) in one pass.
__global__ void build_S_split(const float* __restrict__ Sf, float* __restrict__ S,
                              __nv_bfloat16* __restrict__ hi, __nv_bfloat16* __restrict__ lo,
                              __nv_bfloat16* __restrict__ nhi, __nv_bfloat16* __restrict__ nlo) {
    int idx = blockIdx.x * blockDim.x + threadIdx.x;
    if (idx >= NN) return;
    int r = idx >> 11;
    int c = idx & (Ndim - 1);
    float v = 0.0f;
    if (r < c)      v =  Sf[r * (2 * Ndim - r - 1) / 2 + (c - r - 1)];
    else if (r > c) v = -Sf[c * (2 * Ndim - c - 1) / 2 + (r - c - 1)];
    S[idx] = v;
    __nv_bfloat16 h = __float2bfloat16(v);
    __nv_bfloat16 l = __float2bfloat16(v - __bfloat162float(h));
    hi[idx] = h; lo[idx] = l;
    nhi[idx] = __hneg(h); nlo[idx] = __hneg(l);
}

__global__ void split_plain(const float* __restrict__ src,
                            __nv_bfloat16* __restrict__ hi, __nv_bfloat16* __restrict__ lo,
                            int n) {
    int i = blockIdx.x * blockDim.x + threadIdx.x;
    if (i >= n) return;
    float x = src[i];
    __nv_bfloat16 h = __float2bfloat16(x);
    hi[i] = h;
    lo[i] = __float2bfloat16(x - __bfloat162float(h));
}

// R1^T = C6*I - C7*S + C8*S2 - C9*W  -> split directly to bf16 hi/lo
__global__ void lincomb_R1t_split(const float* __restrict__ S, const float* __restrict__ S2,
                                  const float* __restrict__ W,
                                  __nv_bfloat16* __restrict__ hi, __nv_bfloat16* __restrict__ lo) {
    int idx = blockIdx.x * blockDim.x + threadIdx.x;
    if (idx >= NN) return;
    int r = idx >> 11;
    int c = idx & (Ndim - 1);
    float v = -C7 * S[idx] + C8 * S2[idx] - C9 * W[idx];
    if (r == c) v += C6;
    __nv_bfloat16 h = __float2bfloat16(v);
    hi[idx] = h;
    lo[idx] = __float2bfloat16(v - __bfloat162float(h));
}

// ---------------------------------------------------------------------------
// HMMA split-bf16 GEMM:
//   D[M,Nc] (fp32) = (Ahi+Alo)[M,K] @ ((Bthi+Btlo)[Nc,K])^T   (hh + lh + hl)
//   + eI*I + e1*E1 + e2*E2 (fp32, nullable)
//   outputs: Cf (fp32, nullable) and/or (Ho,Lo2) bf16 split pair (nullable)
// CTA tile 128x128, BK=32, 3-stage cp.async pipeline, 256 threads (8 warps,
// warp tile 64x32). XOR-swizzled smem (no padding): 96KB -> 2 CTAs/SM.
// One __syncthreads per k-iteration.
// ---------------------------------------------------------------------------
#define BKC     32
#define STAGES  3
#define TILE_B  8192                  // 128 rows x 64 B
#define STAGE_B (4 * TILE_B)          // Ahi, Alo, Bhi, Blo
#define SMEM_B  (STAGES * STAGE_B)    // 98304 bytes

__global__ __launch_bounds__(256, 2)
void mma_gemm(const __nv_bfloat16* __restrict__ Ahi, const __nv_bfloat16* __restrict__ Alo,
              const __nv_bfloat16* __restrict__ Bthi, const __nv_bfloat16* __restrict__ Btlo,
              float* __restrict__ Cf,
              __nv_bfloat16* __restrict__ Ho, __nv_bfloat16* __restrict__ Lo2,
              const float* __restrict__ E1, float e1,
              const float* __restrict__ E2, float e2, float eI,
              int M, int Nc, int K)
{
    extern __shared__ __align__(128) char sm[];
    const uint32_t smu = smem_to_u32(sm);

    const int tid  = threadIdx.x;
    const int lane = tid & 31;
    const int wid  = tid >> 5;
    const int wrow = wid & 1;          // 2 warp-rows of 64
    const int wcol = wid >> 1;         // 4 warp-cols of 32
    const int rl   = lane & 7;
    const int gq   = lane >> 3;

    const int rowA = blockIdx.y * 128;
    const int rowB = blockIdx.x * 128;

    // per-lane ldmatrix row/chunk bases within a tile
    const int arow = rl + (gq & 1) * 8 + wrow * 64;   // + mt*16
    const int achk = gq >> 1;                         // + ks*2
    const int brow = rl + (gq >> 1) * 8 + wcol * 32;  // + ng*16
    const int bchk = gq & 1;                          // + ks*2

    // gmem load assignment: 512 16B-chunks per tile, 2 per thread
    const int ldrow0 = tid >> 2;              // rows 0..63
    const int ldc    = tid & 3;               // 16B chunk in row
    const uint32_t so0 = swz(ldrow0,      ldc);
    const uint32_t so1 = swz(ldrow0 + 64, ldc);

    float acc[64];
#pragma unroll
    for (int i = 0; i < 64; i++) acc[i] = 0.0f;

    const int nt = K / BKC;

    auto issue = [&](int kt, int stage) {
        const int kc = kt * BKC;
        const uint32_t sb = smu + stage * STAGE_B;
        const size_t ga0 = (size_t)(rowA + ldrow0)      * K + kc + ldc * 8;
        const size_t ga1 = (size_t)(rowA + ldrow0 + 64) * K + kc + ldc * 8;
        const size_t gb0 = (size_t)(rowB + ldrow0)      * K + kc + ldc * 8;
        const size_t gb1 = (size_t)(rowB + ldrow0 + 64) * K + kc + ldc * 8;
        cp16(sb + so0,              Ahi  + ga0);
        cp16(sb + so1,              Ahi  + ga1);
        cp16(sb + TILE_B + so0,     Alo  + ga0);
        cp16(sb + TILE_B + so1,     Alo  + ga1);
        cp16(sb + 2 * TILE_B + so0, Bthi + gb0);
        cp16(sb + 2 * TILE_B + so1, Bthi + gb1);
        cp16(sb + 3 * TILE_B + so0, Btlo + gb0);
        cp16(sb + 3 * TILE_B + so1, Btlo + gb1);
    };

    issue(0, 0); CP_COMMIT();
    issue(1, 1); CP_COMMIT();

    int stage = 0;
    for (int kt = 0; kt < nt; kt++) {
        CP_WAIT(1);
        __syncthreads();
        // refill the stage all warps just finished with (proven by the barrier)
        if (kt + 2 < nt) issue(kt + 2, (stage + 2) % STAGES);
        CP_COMMIT();   // commit every iter (possibly empty) to keep counts uniform

        const uint32_t sb = smu + stage * STAGE_B;
#pragma unroll
        for (int ks = 0; ks < 2; ks++) {
            // hh: A-hi x B-hi
            uint32_t ah[16], bh[8];
#pragma unroll
            for (int mt = 0; mt < 4; mt++)
                ldm_x4(ah + mt * 4, sb + swz(arow + mt * 16, achk + ks * 2));
#pragma unroll
            for (int ng = 0; ng < 2; ng++)
                ldm_x4(bh + ng * 4, sb + 2 * TILE_B + swz(brow + ng * 16, bchk + ks * 2));
#pragma unroll
            for (int mt = 0; mt < 4; mt++)
#pragma unroll
                for (int n8 = 0; n8 < 4; n8++) {
                    const int bi = (n8 >> 1) * 4 + (n8 & 1) * 2;
                    mma16816(acc + (mt * 4 + n8) * 4, ah + mt * 4, bh[bi], bh[bi + 1]);
                }
            // lh: A-lo x B-hi (bh still live, then dies)
            uint32_t al[16];
#pragma unroll
            for (int mt = 0; mt < 4; mt++)
                ldm_x4(al + mt * 4, sb + TILE_B + swz(arow + mt * 16, achk + ks * 2));
#pragma unroll
            for (int mt = 0; mt < 4; mt++)
#pragma unroll
                for (int n8 = 0; n8 < 4; n8++) {
                    const int bi = (n8 >> 1) * 4 + (n8 & 1) * 2;
                    mma16816(acc + (mt * 4 + n8) * 4, al + mt * 4, bh[bi], bh[bi + 1]);
                }
            // hl: A-hi x B-lo (ah still live)
            uint32_t bl[8];
#pragma unroll
            for (int ng = 0; ng < 2; ng++)
                ldm_x4(bl + ng * 4, sb + 3 * TILE_B + swz(brow + ng * 16, bchk + ks * 2));
#pragma unroll
            for (int mt = 0; mt < 4; mt++)
#pragma unroll
                for (int n8 = 0; n8 < 4; n8++) {
                    const int bi = (n8 >> 1) * 4 + (n8 & 1) * 2;
                    mma16816(acc + (mt * 4 + n8) * 4, ah + mt * 4, bl[bi], bl[bi + 1]);
                }
        }
        stage = (stage + 1) % STAGES;
    }

    // ---------------- epilogue --------------------------------------------
    const int rbase = rowA + wrow * 64 + (lane >> 2);
    const int cbase = rowB + wcol * 32 + (lane & 3) * 2;

#pragma unroll
    for (int mt = 0; mt < 4; mt++) {
#pragma unroll
        for (int n8 = 0; n8 < 4; n8++) {
            const float* c = acc + (mt * 4 + n8) * 4;
            const int col = cbase + n8 * 8;
#pragma unroll
            for (int h = 0; h < 2; h++) {
                const int r = rbase + mt * 16 + h * 8;
                float v0 = c[h * 2], v1 = c[h * 2 + 1];
                const size_t off = (size_t)r * Nc + col;
                if (E1) {
                    float2 e = *reinterpret_cast<const float2*>(E1 + off);
                    v0 += e1 * e.x; v1 += e1 * e.y;
                }
                if (E2) {
                    float2 e = *reinterpret_cast<const float2*>(E2 + off);
                    v0 += e2 * e.x; v1 += e2 * e.y;
                }
                if (eI != 0.0f) {
                    if (r == col)     v0 += eI;
                    if (r == col + 1) v1 += eI;
                }
                if (Cf)
                    *reinterpret_cast<float2*>(Cf + off) = make_float2(v0, v1);
                if (Ho) {
                    __nv_bfloat16 h0 = __float2bfloat16(v0);
                    __nv_bfloat16 h1 = __float2bfloat16(v1);
                    __nv_bfloat16 l0 = __float2bfloat16(v0 - __bfloat162float(h0));
                    __nv_bfloat16 l1 = __float2bfloat16(v1 - __bfloat162float(h1));
                    uint32_t hp = (uint32_t)__bfloat16_as_ushort(h0) |
                                  ((uint32_t)__bfloat16_as_ushort(h1) << 16);
                    uint32_t lp = (uint32_t)__bfloat16_as_ushort(l0) |
                                  ((uint32_t)__bfloat16_as_ushort(l1) << 16);
                    *reinterpret_cast<uint32_t*>(Ho  + off) = hp;
                    *reinterpret_cast<uint32_t*>(Lo2 + off) = lp;
                }
            }
        }
    }
}

// ---------------------------------------------------------------------------
extern "C" void kernel_launch(void* const* d_in, const int* in_sizes, int n_in,
                              void* d_out, int out_size) {
    const float* X;
    const float* Sf;
    if (in_sizes[0] == NFLAT) { Sf = (const float*)d_in[0]; X = (const float*)d_in[1]; }
    else                      { X  = (const float*)d_in[0]; Sf = (const float*)d_in[1]; }
    float* Y = (float*)d_out;

    float *S, *S2, *W;
    __nv_bfloat16 *Shi, *Slo, *Snhi, *Snlo, *S2hi, *S2lo, *Whi, *Wlo;
    __nv_bfloat16 *R1thi, *R1tlo, *R2thi, *R2tlo, *Qthi, *Qtlo, *Xhi, *Xlo;
    cudaGetSymbolAddress((void**)&S,   g_S);
    cudaGetSymbolAddress((void**)&S2,  g_S2);
    cudaGetSymbolAddress((void**)&W,   g_W);
    cudaGetSymbolAddress((void**)&Shi,  g_Shi);  cudaGetSymbolAddress((void**)&Slo,  g_Slo);
    cudaGetSymbolAddress((void**)&Snhi, g_Snhi); cudaGetSymbolAddress((void**)&Snlo, g_Snlo);
    cudaGetSymbolAddress((void**)&S2hi, g_S2hi); cudaGetSymbolAddress((void**)&S2lo, g_S2lo);
    cudaGetSymbolAddress((void**)&Whi,  g_Whi);  cudaGetSymbolAddress((void**)&Wlo,  g_Wlo);
    cudaGetSymbolAddress((void**)&R1thi, g_R1thi); cudaGetSymbolAddress((void**)&R1tlo, g_R1tlo);
    cudaGetSymbolAddress((void**)&R2thi, g_R2thi); cudaGetSymbolAddress((void**)&R2tlo, g_R2tlo);
    cudaGetSymbolAddress((void**)&Qthi,  g_Qthi);  cudaGetSymbolAddress((void**)&Qtlo,  g_Qtlo);
    cudaGetSymbolAddress((void**)&Xhi,  g_Xhi);  cudaGetSymbolAddress((void**)&Xlo,  g_Xlo);

    cudaFuncSetAttribute(mma_gemm, cudaFuncAttributeMaxDynamicSharedMemorySize, SMEM_B);

    build_S_split<<<NN / 256, 256>>>(Sf, S, Shi, Slo, Snhi, Snlo);
    split_plain<<<(BATCHN * Ndim) / 256, 256>>>(X, Xhi, Xlo, BATCHN * Ndim);

    dim3 gSq(Ndim / 128, Ndim / 128);   // 16 x 16

    // S2 = S @ S      (Bt = -S  =>  D = S @ (-S)^T = S@S). out: fp32 + splits
    mma_gemm<<<gSq, 256, SMEM_B>>>(Shi, Slo, Snhi, Snlo,
                                   S2, S2hi, S2lo,
                                   nullptr, 0.f, nullptr, 0.f, 0.f,
                                   Ndim, Ndim, Ndim);
    // W = S2 @ S      out: fp32 + splits
    mma_gemm<<<gSq, 256, SMEM_B>>>(S2hi, S2lo, Snhi, Snlo,
                                   W, Whi, Wlo,
                                   nullptr, 0.f, nullptr, 0.f, 0.f,
                                   Ndim, Ndim, Ndim);
    // R1^T = C6 I - C7 S + C8 S2 - C9 W  (elementwise, split directly)
    lincomb_R1t_split<<<NN / 256, 256>>>(S, S2, W, R1thi, R1tlo);

    // R2^T = R1^T @ (-W) + C3 I - C4 S + C5 S2   (Bt = W since (-W)^T = W)
    mma_gemm<<<gSq, 256, SMEM_B>>>(R1thi, R1tlo, Whi, Wlo,
                                   nullptr, R2thi, R2tlo,
                                   S, -C4, S2, C5, C3,
                                   Ndim, Ndim, Ndim);
    // Q^T  = R2^T @ (-W) + C0 I - C1 S + C2 S2
    mma_gemm<<<gSq, 256, SMEM_B>>>(R2thi, R2tlo, Whi, Wlo,
                                   nullptr, Qthi, Qtlo,
                                   S, -C1, S2, C2, C0,
                                   Ndim, Ndim, Ndim);
    // Y = X @ Q       (Bt = Q^T row-major = Qt). out: fp32 -> d_out
    dim3 gY(Ndim / 128, BATCHN / 128);  // 16 x 64
    mma_gemm<<<gY, 256, SMEM_B>>>(Xhi, Xlo, Qthi, Qtlo,
                                  Y, nullptr, nullptr,
                                  nullptr, 0.f, nullptr, 0.f, 0.f,
                                  BATCHN, Ndim, Ndim);
}

// round 12
// speedup vs baseline: 6.1262x; 1.2987x over previous
#include <cuda_runtime.h>
#include <cuda_bf16.h>
#include <cstdint>

#define Ndim  2048
#define NN    (Ndim * Ndim)
#define NFLAT (Ndim * (Ndim - 1) / 2)
#define BATCHN 8192
#define NT128 (Ndim / 128)            // 16 tiles per dim

// Taylor coefficients 1/i!
#define C0 1.0f
#define C1 1.0f
#define C2 0.5f
#define C3 1.6666666666666666e-1f
#define C4 4.1666666666666664e-2f
#define C5 8.3333333333333332e-3f
#define C6 1.3888888888888889e-3f
#define C7 1.9841269841269841e-4f
#define C8 2.4801587301587302e-5f
#define C9 2.7557319223985893e-6f

// ---------------- scratch (__device__ globals; allocation-free rule) -------
__device__ float    g_S  [NN];
__device__ float    g_S2 [NN];
__device__ uint32_t g_Stf [NN];    // tf32 bit patterns
__device__ uint32_t g_Sntf[NN];    // tf32 of -S
__device__ uint32_t g_S2tf[NN];
__device__ uint32_t g_Wf  [NN];    // W fp32 (as u32 for mirror); reinterpreted float
__device__ uint32_t g_Wtf [NN];
__device__ uint32_t g_R1tf[NN];
__device__ uint32_t g_R2tf[NN];
__device__ __nv_bfloat16 g_Qthi[NN], g_Qtlo[NN];
__device__ __nv_bfloat16 g_Xhi[BATCHN * Ndim], g_Xlo[BATCHN * Ndim];

// ---------------------- PTX helpers (base-target legal only) ---------------
__device__ __forceinline__ uint32_t smem_to_u32(const void* p) {
    uint32_t a;
    asm("{ .reg .u64 t; cvta.to.shared.u64 t, %1; cvt.u32.u64 %0, t; }"
        : "=r"(a) : "l"(p));
    return a;
}
__device__ __forceinline__ void cp16(uint32_t s, const void* g) {
    asm volatile("cp.async.cg.shared.global [%0], [%1], 16;" :: "r"(s), "l"(g));
}
#define CP_COMMIT() asm volatile("cp.async.commit_group;" ::: "memory")
#define CP_WAIT(n)  asm volatile("cp.async.wait_group %0;" :: "n"(n) : "memory")

__device__ __forceinline__ void ldm_x4(uint32_t* r, uint32_t addr) {
    asm volatile("ldmatrix.sync.aligned.m8n8.x4.shared.b16 {%0,%1,%2,%3}, [%4];"
                 : "=r"(r[0]), "=r"(r[1]), "=r"(r[2]), "=r"(r[3]) : "r"(addr));
}
__device__ __forceinline__ void mma16816(float* c, const uint32_t* a,
                                         uint32_t b0, uint32_t b1) {
    asm volatile(
        "mma.sync.aligned.m16n8k16.row.col.f32.bf16.bf16.f32 "
        "{%0,%1,%2,%3}, {%4,%5,%6,%7}, {%8,%9}, {%0,%1,%2,%3};"
        : "+f"(c[0]), "+f"(c[1]), "+f"(c[2]), "+f"(c[3])
        : "r"(a[0]), "r"(a[1]), "r"(a[2]), "r"(a[3]), "r"(b0), "r"(b1));
}
__device__ __forceinline__ void mma1688tf(float* c, const uint32_t* a,
                                          uint32_t b0, uint32_t b1) {
    asm volatile(
        "mma.sync.aligned.m16n8k8.row.col.f32.tf32.tf32.f32 "
        "{%0,%1,%2,%3}, {%4,%5,%6,%7}, {%8,%9}, {%0,%1,%2,%3};"
        : "+f"(c[0]), "+f"(c[1]), "+f"(c[2]), "+f"(c[3])
        : "r"(a[0]), "r"(a[1]), "r"(a[2]), "r"(a[3]), "r"(b0), "r"(b1));
}
__device__ __forceinline__ uint32_t f2tf(float x) {
    uint32_t u;
    asm("cvt.rna.tf32.f32 %0, %1;" : "=r"(u) : "f"(x));
    return u;
}

// swizzles: bf16 tile rows = 64B (4 chunks), tf32 tile rows = 128B (8 chunks)
__device__ __forceinline__ uint32_t swz64(int row, int chunk) {
    return (uint32_t)(row * 64 + ((chunk ^ ((row >> 1) & 3)) << 4));
}
__device__ __forceinline__ uint32_t swz128(int row, int chunk) {
    return (uint32_t)(row * 128 + ((chunk ^ (row & 7)) << 4));
}

// ---------------------- preprocessing kernels ------------------------------
// Build antisymmetric S (fp32) and tf32 versions of S and -S in one pass.
__global__ void build_S_tf(const float* __restrict__ Sf, float* __restrict__ S,
                           uint32_t* __restrict__ Stf, uint32_t* __restrict__ Sntf) {
    int idx = blockIdx.x * blockDim.x + threadIdx.x;
    if (idx >= NN) return;
    int r = idx >> 11;
    int c = idx & (Ndim - 1);
    float v = 0.0f;
    if (r < c)      v =  Sf[r * (2 * Ndim - r - 1) / 2 + (c - r - 1)];
    else if (r > c) v = -Sf[c * (2 * Ndim - c - 1) / 2 + (r - c - 1)];
    S[idx] = v;
    uint32_t t = f2tf(v);
    Stf[idx]  = t;
    Sntf[idx] = t ^ 0x80000000u;   // rna is sign-symmetric
}

__global__ void split_plain(const float* __restrict__ src,
                            __nv_bfloat16* __restrict__ hi, __nv_bfloat16* __restrict__ lo,
                            int n) {
    int i = blockIdx.x * blockDim.x + threadIdx.x;
    if (i >= n) return;
    float x = src[i];
    __nv_bfloat16 h = __float2bfloat16(x);
    hi[i] = h;
    lo[i] = __float2bfloat16(x - __bfloat162float(h));
}

// R1^T = C6*I - C7*S + C8*S2 - C9*W  -> tf32
__global__ void lincomb_R1t_tf(const float* __restrict__ S, const float* __restrict__ S2,
                               const float* __restrict__ W, uint32_t* __restrict__ out) {
    int idx = blockIdx.x * blockDim.x + threadIdx.x;
    if (idx >= NN) return;
    int r = idx >> 11;
    int c = idx & (Ndim - 1);
    float v = -C7 * S[idx] + C8 * S2[idx] - C9 * W[idx];
    if (r == c) v += C6;
    out[idx] = f2tf(v);
}

// Mirror strictly-lower 128-tiles from upper: dst[r,c] = src[c,r] ^ sgn.
// Works on two u32 arrays at once (fp32 and tf32 bit patterns; sign bit xor).
__global__ void mirror_pair(uint32_t* __restrict__ A0, uint32_t* __restrict__ A1,
                            uint32_t sgn) {
    int t = blockIdx.y;                 // lower-tile linear index, 0..119
    int i = 1, rem = t;
    while (rem >= i) { rem -= i; i++; }
    int j = rem;                        // dest tile (i, j), i > j
    int sub = blockIdx.x;               // 16 sub-blocks of 32x32
    int sr = (sub >> 2) * 32, sc = (sub & 3) * 32;
    __shared__ uint32_t s0[32][33], s1[32][33];
    int tx = threadIdx.x, ty = threadIdx.y;        // 32 x 8
    // source region: rows j*128+sc+.., cols i*128+sr+..  (coalesced reads)
#pragma unroll
    for (int q = 0; q < 4; q++) {
        int srow = j * 128 + sc + ty + q * 8;
        int scol = i * 128 + sr + tx;
        s0[ty + q * 8][tx] = A0[(size_t)srow * Ndim + scol];
        s1[ty + q * 8][tx] = A1[(size_t)srow * Ndim + scol];
    }
    __syncthreads();
#pragma unroll
    for (int q = 0; q < 4; q++) {
        int drow = i * 128 + sr + ty + q * 8;
        int dcol = j * 128 + sc + tx;
        A0[(size_t)drow * Ndim + dcol] = s0[tx][ty + q * 8] ^ sgn;
        A1[(size_t)drow * Ndim + dcol] = s1[tx][ty + q * 8] ^ sgn;
    }
}

// ---------------------------------------------------------------------------
// tf32 single-product GEMM:  D[M,Nc] = A[M,K] @ (Bt[Nc,K])^T
//   + eI*I + e1*E1 + e2*E2 (fp32, nullable)
//   outputs: Cf (fp32, nullable), Ct (tf32 u32, nullable), (Hb,Lb) bf16 (nullable)
// CTA tile 128x128, BK=32 fp32, 3-stage cp.async, 256 threads, warp 64x32.
// tri != 0: blockIdx.x is a linear upper-triangle tile id (j >= i).
// ---------------------------------------------------------------------------
#define T_TILE_B  16384               // 128 rows x 128 B
#define T_STAGE_B (2 * T_TILE_B)      // A + Bt
#define T_SMEM_B  (3 * T_STAGE_B)     // 98304

__global__ __launch_bounds__(256, 2)
void tf32_gemm(const uint32_t* __restrict__ A, const uint32_t* __restrict__ Bt,
               float* __restrict__ Cf, uint32_t* __restrict__ Ct,
               __nv_bfloat16* __restrict__ Hb, __nv_bfloat16* __restrict__ Lb,
               const float* __restrict__ E1, float e1,
               const float* __restrict__ E2, float e2, float eI,
               int M, int Nc, int K, int tri)
{
    extern __shared__ __align__(128) char sm[];
    const uint32_t smu = smem_to_u32(sm);

    const int tid  = threadIdx.x;
    const int lane = tid & 31;
    const int wid  = tid >> 5;
    const int wrow = wid & 1;
    const int wcol = wid >> 1;
    const int rl   = lane & 7;
    const int gq   = lane >> 3;

    int bx, by;
    if (tri) {
        int t = blockIdx.x, i = 0;
        while (t >= NT128 - i) { t -= NT128 - i; i++; }
        by = i; bx = i + t;           // j >= i
    } else {
        bx = blockIdx.x; by = blockIdx.y;
    }
    const int rowA = by * 128;
    const int rowB = bx * 128;

    const int arow = rl + (gq & 1) * 8 + wrow * 64;   // + mt*16
    const int achk = gq >> 1;                         // + ks*2
    const int brow = rl + (gq >> 1) * 8 + wcol * 32;  // + ng*16
    const int bchk = gq & 1;                          // + ks*2

    // gmem loads: 1024 16B-chunks per tile, 4 per thread per tile
    const int ldrow = tid >> 3;               // base rows 0..31 (x4 steps of 32)
    const int ldc   = tid & 7;

    float acc[64];
#pragma unroll
    for (int i = 0; i < 64; i++) acc[i] = 0.0f;

    const int nt = K / 32;

    auto issue = [&](int kt, int stage) {
        const int kc = kt * 32;
        const uint32_t sb = smu + stage * T_STAGE_B;
#pragma unroll
        for (int q = 0; q < 4; q++) {
            const int row = ldrow + q * 32;
            const uint32_t so = swz128(row, ldc);
            cp16(sb + so,            A  + (size_t)(rowA + row) * K + kc + ldc * 4);
            cp16(sb + T_TILE_B + so, Bt + (size_t)(rowB + row) * K + kc + ldc * 4);
        }
    };

    issue(0, 0); CP_COMMIT();
    issue(1, 1); CP_COMMIT();

    int stage = 0;
    for (int kt = 0; kt < nt; kt++) {
        CP_WAIT(1);
        __syncthreads();
        if (kt + 2 < nt) issue(kt + 2, (stage + 2) % 3);
        CP_COMMIT();

        const uint32_t sb = smu + stage * T_STAGE_B;
#pragma unroll
        for (int ks = 0; ks < 4; ks++) {
            uint32_t ah[16], bh[8];
#pragma unroll
            for (int mt = 0; mt < 4; mt++)
                ldm_x4(ah + mt * 4, sb + swz128(arow + mt * 16, achk + ks * 2));
#pragma unroll
            for (int ng = 0; ng < 2; ng++)
                ldm_x4(bh + ng * 4, sb + T_TILE_B + swz128(brow + ng * 16, bchk + ks * 2));
#pragma unroll
            for (int mt = 0; mt < 4; mt++)
#pragma unroll
                for (int n8 = 0; n8 < 4; n8++) {
                    const int bi = (n8 >> 1) * 4 + (n8 & 1) * 2;
                    mma1688tf(acc + (mt * 4 + n8) * 4, ah + mt * 4, bh[bi], bh[bi + 1]);
                }
        }
        stage = (stage + 1) % 3;
    }

    // ---------------- epilogue --------------------------------------------
    const int rbase = rowA + wrow * 64 + (lane >> 2);
    const int cbase = rowB + wcol * 32 + (lane & 3) * 2;

#pragma unroll
    for (int mt = 0; mt < 4; mt++) {
#pragma unroll
        for (int n8 = 0; n8 < 4; n8++) {
            const float* c = acc + (mt * 4 + n8) * 4;
            const int col = cbase + n8 * 8;
#pragma unroll
            for (int h = 0; h < 2; h++) {
                const int r = rbase + mt * 16 + h * 8;
                float v0 = c[h * 2], v1 = c[h * 2 + 1];
                const size_t off = (size_t)r * Nc + col;
                if (E1) {
                    float2 e = *reinterpret_cast<const float2*>(E1 + off);
                    v0 += e1 * e.x; v1 += e1 * e.y;
                }
                if (E2) {
                    float2 e = *reinterpret_cast<const float2*>(E2 + off);
                    v0 += e2 * e.x; v1 += e2 * e.y;
                }
                if (eI != 0.0f) {
                    if (r == col)     v0 += eI;
                    if (r == col + 1) v1 += eI;
                }
                if (Cf)
                    *reinterpret_cast<float2*>(Cf + off) = make_float2(v0, v1);
                if (Ct) {
                    uint2 t = make_uint2(f2tf(v0), f2tf(v1));
                    *reinterpret_cast<uint2*>(Ct + off) = t;
                }
                if (Hb) {
                    __nv_bfloat16 h0 = __float2bfloat16(v0);
                    __nv_bfloat16 h1 = __float2bfloat16(v1);
                    __nv_bfloat16 l0 = __float2bfloat16(v0 - __bfloat162float(h0));
                    __nv_bfloat16 l1 = __float2bfloat16(v1 - __bfloat162float(h1));
                    uint32_t hp = (uint32_t)__bfloat16_as_ushort(h0) |
                                  ((uint32_t)__bfloat16_as_ushort(h1) << 16);
                    uint32_t lp = (uint32_t)__bfloat16_as_ushort(l0) |
                                  ((uint32_t)__bfloat16_as_ushort(l1) << 16);
                    *reinterpret_cast<uint32_t*>(Hb + off) = hp;
                    *reinterpret_cast<uint32_t*>(Lb + off) = lp;
                }
            }
        }
    }
}

// ---------------------------------------------------------------------------
// bf16 3-product GEMM for the final X@Q (verified R11 path, outputs fp32 only)
// ---------------------------------------------------------------------------
#define BKC     32
#define B_TILE  8192                  // 128 rows x 64 B
#define B_STAGE (4 * B_TILE)
#define B_SMEM  (3 * B_STAGE)         // 98304

__global__ __launch_bounds__(256, 2)
void bf16_gemm3(const __nv_bfloat16* __restrict__ Ahi, const __nv_bfloat16* __restrict__ Alo,
                const __nv_bfloat16* __restrict__ Bthi, const __nv_bfloat16* __restrict__ Btlo,
                float* __restrict__ Cf, int M, int Nc, int K)
{
    extern __shared__ __align__(128) char sm[];
    const uint32_t smu = smem_to_u32(sm);

    const int tid  = threadIdx.x;
    const int lane = tid & 31;
    const int wid  = tid >> 5;
    const int wrow = wid & 1;
    const int wcol = wid >> 1;
    const int rl   = lane & 7;
    const int gq   = lane >> 3;

    const int rowA = blockIdx.y * 128;
    const int rowB = blockIdx.x * 128;

    const int arow = rl + (gq & 1) * 8 + wrow * 64;
    const int achk = gq >> 1;
    const int brow = rl + (gq >> 1) * 8 + wcol * 32;
    const int bchk = gq & 1;

    const int ldrow0 = tid >> 2;
    const int ldc    = tid & 3;
    const uint32_t so0 = swz64(ldrow0,      ldc);
    const uint32_t so1 = swz64(ldrow0 + 64, ldc);

    float acc[64];
#pragma unroll
    for (int i = 0; i < 64; i++) acc[i] = 0.0f;

    const int nt = K / BKC;

    auto issue = [&](int kt, int stage) {
        const int kc = kt * BKC;
        const uint32_t sb = smu + stage * B_STAGE;
        const size_t ga0 = (size_t)(rowA + ldrow0)      * K + kc + ldc * 8;
        const size_t ga1 = (size_t)(rowA + ldrow0 + 64) * K + kc + ldc * 8;
        const size_t gb0 = (size_t)(rowB + ldrow0)      * K + kc + ldc * 8;
        const size_t gb1 = (size_t)(rowB + ldrow0 + 64) * K + kc + ldc * 8;
        cp16(sb + so0,              Ahi  + ga0);
        cp16(sb + so1,              Ahi  + ga1);
        cp16(sb + B_TILE + so0,     Alo  + ga0);
        cp16(sb + B_TILE + so1,     Alo  + ga1);
        cp16(sb + 2 * B_TILE + so0, Bthi + gb0);
        cp16(sb + 2 * B_TILE + so1, Bthi + gb1);
        cp16(sb + 3 * B_TILE + so0, Btlo + gb0);
        cp16(sb + 3 * B_TILE + so1, Btlo + gb1);
    };

    issue(0, 0); CP_COMMIT();
    issue(1, 1); CP_COMMIT();

    int stage = 0;
    for (int kt = 0; kt < nt; kt++) {
        CP_WAIT(1);
        __syncthreads();
        if (kt + 2 < nt) issue(kt + 2, (stage + 2) % 3);
        CP_COMMIT();

        const uint32_t sb = smu + stage * B_STAGE;
#pragma unroll
        for (int ks = 0; ks < 2; ks++) {
            uint32_t ah[16], bh[8];
#pragma unroll
            for (int mt = 0; mt < 4; mt++)
                ldm_x4(ah + mt * 4, sb + swz64(arow + mt * 16, achk + ks * 2));
#pragma unroll
            for (int ng = 0; ng < 2; ng++)
                ldm_x4(bh + ng * 4, sb + 2 * B_TILE + swz64(brow + ng * 16, bchk + ks * 2));
#pragma unroll
            for (int mt = 0; mt < 4; mt++)
#pragma unroll
                for (int n8 = 0; n8 < 4; n8++) {
                    const int bi = (n8 >> 1) * 4 + (n8 & 1) * 2;
                    mma16816(acc + (mt * 4 + n8) * 4, ah + mt * 4, bh[bi], bh[bi + 1]);
                }
            uint32_t al[16];
#pragma unroll
            for (int mt = 0; mt < 4; mt++)
                ldm_x4(al + mt * 4, sb + B_TILE + swz64(arow + mt * 16, achk + ks * 2));
#pragma unroll
            for (int mt = 0; mt < 4; mt++)
#pragma unroll
                for (int n8 = 0; n8 < 4; n8++) {
                    const int bi = (n8 >> 1) * 4 + (n8 & 1) * 2;
                    mma16816(acc + (mt * 4 + n8) * 4, al + mt * 4, bh[bi], bh[bi + 1]);
                }
            uint32_t bl[8];
#pragma unroll
            for (int ng = 0; ng < 2; ng++)
                ldm_x4(bl + ng * 4, sb + 3 * B_TILE + swz64(brow + ng * 16, bchk + ks * 2));
#pragma unroll
            for (int mt = 0; mt < 4; mt++)
#pragma unroll
                for (int n8 = 0; n8 < 4; n8++) {
                    const int bi = (n8 >> 1) * 4 + (n8 & 1) * 2;
                    mma16816(acc + (mt * 4 + n8) * 4, ah + mt * 4, bl[bi], bl[bi + 1]);
                }
        }
        stage = (stage + 1) % 3;
    }

    const int rbase = rowA + wrow * 64 + (lane >> 2);
    const int cbase = rowB + wcol * 32 + (lane & 3) * 2;
#pragma unroll
    for (int mt = 0; mt < 4; mt++)
#pragma unroll
        for (int n8 = 0; n8 < 4; n8++) {
            const float* c = acc + (mt * 4 + n8) * 4;
            const int col = cbase + n8 * 8;
#pragma unroll
            for (int h = 0; h < 2; h++) {
                const int r = rbase + mt * 16 + h * 8;
                *reinterpret_cast<float2*>(Cf + (size_t)r * Nc + col) =
                    make_float2(c[h * 2], c[h * 2 + 1]);
            }
        }
}

// ---------------------------------------------------------------------------
extern "C" void kernel_launch(void* const* d_in, const int* in_sizes, int n_in,
                              void* d_out, int out_size) {
    const float* X;
    const float* Sf;
    if (in_sizes[0] == NFLAT) { Sf = (const float*)d_in[0]; X = (const float*)d_in[1]; }
    else                      { X  = (const float*)d_in[0]; Sf = (const float*)d_in[1]; }
    float* Y = (float*)d_out;

    float *S, *S2;
    uint32_t *Stf, *Sntf, *S2tf, *Wf, *Wtf, *R1tf, *R2tf;
    __nv_bfloat16 *Qthi, *Qtlo, *Xhi, *Xlo;
    cudaGetSymbolAddress((void**)&S,    g_S);
    cudaGetSymbolAddress((void**)&S2,   g_S2);
    cudaGetSymbolAddress((void**)&Stf,  g_Stf);
    cudaGetSymbolAddress((void**)&Sntf, g_Sntf);
    cudaGetSymbolAddress((void**)&S2tf, g_S2tf);
    cudaGetSymbolAddress((void**)&Wf,   g_Wf);
    cudaGetSymbolAddress((void**)&Wtf,  g_Wtf);
    cudaGetSymbolAddress((void**)&R1tf, g_R1tf);
    cudaGetSymbolAddress((void**)&R2tf, g_R2tf);
    cudaGetSymbolAddress((void**)&Qthi, g_Qthi);
    cudaGetSymbolAddress((void**)&Qtlo, g_Qtlo);
    cudaGetSymbolAddress((void**)&Xhi,  g_Xhi);
    cudaGetSymbolAddress((void**)&Xlo,  g_Xlo);

    cudaFuncSetAttribute(tf32_gemm,  cudaFuncAttributeMaxDynamicSharedMemorySize, T_SMEM_B);
    cudaFuncSetAttribute(bf16_gemm3, cudaFuncAttributeMaxDynamicSharedMemorySize, B_SMEM);

    build_S_tf<<<NN / 256, 256>>>(Sf, S, Stf, Sntf);
    split_plain<<<(BATCHN * Ndim) / 256, 256>>>(X, Xhi, Xlo, BATCHN * Ndim);

    const int nTriUp  = NT128 * (NT128 + 1) / 2;    // 136
    const int nTriLow = NT128 * (NT128 - 1) / 2;    // 120
    dim3 gSq(NT128, NT128);
    dim3 gMir(16, nTriLow), bMir(32, 8);

    // S2 = S @ S  (upper tiles; D = S @ (-S)^T). out: fp32 + tf32. symmetric.
    tf32_gemm<<<nTriUp, 256, T_SMEM_B>>>(Stf, Sntf,
                                         S2, S2tf, nullptr, nullptr,
                                         nullptr, 0.f, nullptr, 0.f, 0.f,
                                         Ndim, Ndim, Ndim, 1);
    mirror_pair<<<gMir, bMir>>>((uint32_t*)S2, S2tf, 0u);

    // W = S2 @ S  (upper tiles). out: fp32 + tf32. antisymmetric.
    tf32_gemm<<<nTriUp, 256, T_SMEM_B>>>(S2tf, Sntf,
                                         (float*)Wf, Wtf, nullptr, nullptr,
                                         nullptr, 0.f, nullptr, 0.f, 0.f,
                                         Ndim, Ndim, Ndim, 1);
    mirror_pair<<<gMir, bMir>>>(Wf, Wtf, 0x80000000u);

    // R1^T = C6 I - C7 S + C8 S2 - C9 W
    lincomb_R1t_tf<<<NN / 256, 256>>>(S, S2, (const float*)Wf, R1tf);

    // R2^T = R1^T @ (-W) + C3 I - C4 S + C5 S2    (Bt = W, since (-W)^T = W)
    tf32_gemm<<<gSq, 256, T_SMEM_B>>>(R1tf, Wtf,
                                      nullptr, R2tf, nullptr, nullptr,
                                      S, -C4, S2, C5, C3,
                                      Ndim, Ndim, Ndim, 0);
    // Q^T  = R2^T @ (-W) + C0 I - C1 S + C2 S2    -> bf16 hi/lo split
    tf32_gemm<<<gSq, 256, T_SMEM_B>>>(R2tf, Wtf,
                                      nullptr, nullptr, Qthi, Qtlo,
                                      S, -C1, S2, C2, C0,
                                      Ndim, Ndim, Ndim, 0);
    // Y = X @ Q   (Bt = Q^T row-major = Qt), bf16 3-product
    dim3 gY(NT128, BATCHN / 128);
    bf16_gemm3<<<gY, 256, B_SMEM>>>(Xhi, Xlo, Qthi, Qtlo, Y, BATCHN, Ndim, Ndim);
}

// round 13
// speedup vs baseline: 7.8494x; 1.2813x over previous
#include <cuda_runtime.h>
#include <cuda_bf16.h>
#include <cstdint>

#define Ndim  2048
#define NN    (Ndim * Ndim)
#define NFLAT (Ndim * (Ndim - 1) / 2)
#define BATCHN 8192
#define NT128 (Ndim / 128)            // 16 tiles per dim

// Taylor coefficients 1/i!
#define C0 1.0f
#define C1 1.0f
#define C2 0.5f
#define C3 1.6666666666666666e-1f
#define C4 4.1666666666666664e-2f
#define C5 8.3333333333333332e-3f
#define C6 1.3888888888888889e-3f
#define C7 1.9841269841269841e-4f
#define C8 2.4801587301587302e-5f
#define C9 2.7557319223985893e-6f

// ---------------- scratch (__device__ globals; allocation-free rule) -------
__device__ float    g_S  [NN];
__device__ float    g_S2 [NN];
__device__ uint32_t g_Stf [NN];    // tf32 bit patterns
__device__ uint32_t g_Sntf[NN];    // tf32 of -S
__device__ uint32_t g_S2tf[NN];
__device__ uint32_t g_Wf  [NN];    // W fp32 (as u32 for mirror)
__device__ uint32_t g_Wtf [NN];
__device__ uint32_t g_R1tf[NN];
__device__ uint32_t g_R2tf[NN];
__device__ uint32_t g_Qttf[NN];    // Q^T in tf32
__device__ uint32_t g_Xtf [BATCHN * Ndim];

// ---------------------- PTX helpers (base-target legal only) ---------------
__device__ __forceinline__ uint32_t smem_to_u32(const void* p) {
    uint32_t a;
    asm("{ .reg .u64 t; cvta.to.shared.u64 t, %1; cvt.u32.u64 %0, t; }"
        : "=r"(a) : "l"(p));
    return a;
}
__device__ __forceinline__ void cp16(uint32_t s, const void* g) {
    asm volatile("cp.async.cg.shared.global [%0], [%1], 16;" :: "r"(s), "l"(g));
}
#define CP_COMMIT() asm volatile("cp.async.commit_group;" ::: "memory")
#define CP_WAIT(n)  asm volatile("cp.async.wait_group %0;" :: "n"(n) : "memory")

__device__ __forceinline__ void ldm_x4(uint32_t* r, uint32_t addr) {
    asm volatile("ldmatrix.sync.aligned.m8n8.x4.shared.b16 {%0,%1,%2,%3}, [%4];"
                 : "=r"(r[0]), "=r"(r[1]), "=r"(r[2]), "=r"(r[3]) : "r"(addr));
}
__device__ __forceinline__ void mma1688tf(float* c, const uint32_t* a,
                                          uint32_t b0, uint32_t b1) {
    asm volatile(
        "mma.sync.aligned.m16n8k8.row.col.f32.tf32.tf32.f32 "
        "{%0,%1,%2,%3}, {%4,%5,%6,%7}, {%8,%9}, {%0,%1,%2,%3};"
        : "+f"(c[0]), "+f"(c[1]), "+f"(c[2]), "+f"(c[3])
        : "r"(a[0]), "r"(a[1]), "r"(a[2]), "r"(a[3]), "r"(b0), "r"(b1));
}
__device__ __forceinline__ uint32_t f2tf(float x) {
    uint32_t u;
    asm("cvt.rna.tf32.f32 %0, %1;" : "=r"(u) : "f"(x));
    return u;
}

// tf32 tile rows = 128B (8 x 16B chunks), XOR swizzle
__device__ __forceinline__ uint32_t swz128(int row, int chunk) {
    return (uint32_t)(row * 128 + ((chunk ^ (row & 7)) << 4));
}

// ---------------------- preprocessing kernels ------------------------------
// Build antisymmetric S (fp32) and tf32 versions of S and -S in one pass.
__global__ void build_S_tf(const float* __restrict__ Sf, float* __restrict__ S,
                           uint32_t* __restrict__ Stf, uint32_t* __restrict__ Sntf) {
    int idx = blockIdx.x * blockDim.x + threadIdx.x;
    if (idx >= NN) return;
    int r = idx >> 11;
    int c = idx & (Ndim - 1);
    float v = 0.0f;
    if (r < c)      v =  Sf[r * (2 * Ndim - r - 1) / 2 + (c - r - 1)];
    else if (r > c) v = -Sf[c * (2 * Ndim - c - 1) / 2 + (r - c - 1)];
    S[idx] = v;
    uint32_t t = f2tf(v);
    Stf[idx]  = t;
    Sntf[idx] = t ^ 0x80000000u;   // rna is sign-symmetric
}

// fp32 -> tf32 bulk convert (vectorized)
__global__ void cvt_tf(const float4* __restrict__ src, uint4* __restrict__ dst, int n4) {
    int i = blockIdx.x * blockDim.x + threadIdx.x;
    if (i >= n4) return;
    float4 v = src[i];
    dst[i] = make_uint4(f2tf(v.x), f2tf(v.y), f2tf(v.z), f2tf(v.w));
}

// R1^T = C6*I - C7*S + C8*S2 - C9*W  -> tf32
__global__ void lincomb_R1t_tf(const float* __restrict__ S, const float* __restrict__ S2,
                               const float* __restrict__ W, uint32_t* __restrict__ out) {
    int idx = blockIdx.x * blockDim.x + threadIdx.x;
    if (idx >= NN) return;
    int r = idx >> 11;
    int c = idx & (Ndim - 1);
    float v = -C7 * S[idx] + C8 * S2[idx] - C9 * W[idx];
    if (r == c) v += C6;
    out[idx] = f2tf(v);
}

// Mirror strictly-lower 128-tiles from upper: dst[r,c] = src[c,r] ^ sgn.
__global__ void mirror_pair(uint32_t* __restrict__ A0, uint32_t* __restrict__ A1,
                            uint32_t sgn) {
    int t = blockIdx.y;                 // lower-tile linear index
    int i = 1, rem = t;
    while (rem >= i) { rem -= i; i++; }
    int j = rem;                        // dest tile (i, j), i > j
    int sub = blockIdx.x;               // 16 sub-blocks of 32x32
    int sr = (sub >> 2) * 32, sc = (sub & 3) * 32;
    __shared__ uint32_t s0[32][33], s1[32][33];
    int tx = threadIdx.x, ty = threadIdx.y;        // 32 x 8
#pragma unroll
    for (int q = 0; q < 4; q++) {
        int srow = j * 128 + sc + ty + q * 8;
        int scol = i * 128 + sr + tx;
        s0[ty + q * 8][tx] = A0[(size_t)srow * Ndim + scol];
        s1[ty + q * 8][tx] = A1[(size_t)srow * Ndim + scol];
    }
    __syncthreads();
#pragma unroll
    for (int q = 0; q < 4; q++) {
        int drow = i * 128 + sr + ty + q * 8;
        int dcol = j * 128 + sc + tx;
        A0[(size_t)drow * Ndim + dcol] = s0[tx][ty + q * 8] ^ sgn;
        A1[(size_t)drow * Ndim + dcol] = s1[tx][ty + q * 8] ^ sgn;
    }
}

// ---------------------------------------------------------------------------
// tf32 single-product GEMM:  D[M,Nc] = A[M,K] @ (Bt[Nc,K])^T
//   + eI*I + e1*E1 + e2*E2 (fp32, nullable)
//   outputs: Cf (fp32, nullable), Ct (tf32 u32, nullable)
// CTA tile 128x128, BK=32 fp32, 3-stage cp.async, 256 threads, warp 64x32.
// tri != 0: blockIdx.x is a linear upper-triangle tile id (j >= i).
// ---------------------------------------------------------------------------
#define T_TILE_B  16384               // 128 rows x 128 B
#define T_STAGE_B (2 * T_TILE_B)      // A + Bt
#define T_SMEM_B  (3 * T_STAGE_B)     // 98304

__global__ __launch_bounds__(256, 2)
void tf32_gemm(const uint32_t* __restrict__ A, const uint32_t* __restrict__ Bt,
               float* __restrict__ Cf, uint32_t* __restrict__ Ct,
               const float* __restrict__ E1, float e1,
               const float* __restrict__ E2, float e2, float eI,
               int M, int Nc, int K, int tri)
{
    extern __shared__ __align__(128) char sm[];
    const uint32_t smu = smem_to_u32(sm);

    const int tid  = threadIdx.x;
    const int lane = tid & 31;
    const int wid  = tid >> 5;
    const int wrow = wid & 1;
    const int wcol = wid >> 1;
    const int rl   = lane & 7;
    const int gq   = lane >> 3;

    int bx, by;
    if (tri) {
        int t = blockIdx.x, i = 0;
        while (t >= NT128 - i) { t -= NT128 - i; i++; }
        by = i; bx = i + t;           // j >= i
    } else {
        bx = blockIdx.x; by = blockIdx.y;
    }
    const int rowA = by * 128;
    const int rowB = bx * 128;

    const int arow = rl + (gq & 1) * 8 + wrow * 64;   // + mt*16
    const int achk = gq >> 1;                         // + ks*2
    const int brow = rl + (gq >> 1) * 8 + wcol * 32;  // + ng*16
    const int bchk = gq & 1;                          // + ks*2

    const int ldrow = tid >> 3;               // base rows 0..31 (x4 steps of 32)
    const int ldc   = tid & 7;

    float acc[64];
#pragma unroll
    for (int i = 0; i < 64; i++) acc[i] = 0.0f;

    const int nt = K / 32;

    auto issue = [&](int kt, int stage) {
        const int kc = kt * 32;
        const uint32_t sb = smu + stage * T_STAGE_B;
#pragma unroll
        for (int q = 0; q < 4; q++) {
            const int row = ldrow + q * 32;
            const uint32_t so = swz128(row, ldc);
            cp16(sb + so,            A  + (size_t)(rowA + row) * K + kc + ldc * 4);
            cp16(sb + T_TILE_B + so, Bt + (size_t)(rowB + row) * K + kc + ldc * 4);
        }
    };

    issue(0, 0); CP_COMMIT();
    issue(1, 1); CP_COMMIT();

    int stage = 0;
    for (int kt = 0; kt < nt; kt++) {
        CP_WAIT(1);
        __syncthreads();
        if (kt + 2 < nt) issue(kt + 2, (stage + 2) % 3);
        CP_COMMIT();

        const uint32_t sb = smu + stage * T_STAGE_B;
#pragma unroll
        for (int ks = 0; ks < 4; ks++) {
            uint32_t ah[16], bh[8];
#pragma unroll
            for (int mt = 0; mt < 4; mt++)
                ldm_x4(ah + mt * 4, sb + swz128(arow + mt * 16, achk + ks * 2));
#pragma unroll
            for (int ng = 0; ng < 2; ng++)
                ldm_x4(bh + ng * 4, sb + T_TILE_B + swz128(brow + ng * 16, bchk + ks * 2));
#pragma unroll
            for (int mt = 0; mt < 4; mt++)
#pragma unroll
                for (int n8 = 0; n8 < 4; n8++) {
                    const int bi = (n8 >> 1) * 4 + (n8 & 1) * 2;
                    mma1688tf(acc + (mt * 4 + n8) * 4, ah + mt * 4, bh[bi], bh[bi + 1]);
                }
        }
        stage = (stage + 1) % 3;
    }

    // ---------------- epilogue --------------------------------------------
    const int rbase = rowA + wrow * 64 + (lane >> 2);
    const int cbase = rowB + wcol * 32 + (lane & 3) * 2;

#pragma unroll
    for (int mt = 0; mt < 4; mt++) {
#pragma unroll
        for (int n8 = 0; n8 < 4; n8++) {
            const float* c = acc + (mt * 4 + n8) * 4;
            const int col = cbase + n8 * 8;
#pragma unroll
            for (int h = 0; h < 2; h++) {
                const int r = rbase + mt * 16 + h * 8;
                float v0 = c[h * 2], v1 = c[h * 2 + 1];
                const size_t off = (size_t)r * Nc + col;
                if (E1) {
                    float2 e = *reinterpret_cast<const float2*>(E1 + off);
                    v0 += e1 * e.x; v1 += e1 * e.y;
                }
                if (E2) {
                    float2 e = *reinterpret_cast<const float2*>(E2 + off);
                    v0 += e2 * e.x; v1 += e2 * e.y;
                }
                if (eI != 0.0f) {
                    if (r == col)     v0 += eI;
                    if (r == col + 1) v1 += eI;
                }
                if (Cf)
                    *reinterpret_cast<float2*>(Cf + off) = make_float2(v0, v1);
                if (Ct) {
                    uint2 t = make_uint2(f2tf(v0), f2tf(v1));
                    *reinterpret_cast<uint2*>(Ct + off) = t;
                }
            }
        }
    }
}

// ---------------------------------------------------------------------------
extern "C" void kernel_launch(void* const* d_in, const int* in_sizes, int n_in,
                              void* d_out, int out_size) {
    const float* X;
    const float* Sf;
    if (in_sizes[0] == NFLAT) { Sf = (const float*)d_in[0]; X = (const float*)d_in[1]; }
    else                      { X  = (const float*)d_in[0]; Sf = (const float*)d_in[1]; }
    float* Y = (float*)d_out;

    float *S, *S2;
    uint32_t *Stf, *Sntf, *S2tf, *Wf, *Wtf, *R1tf, *R2tf, *Qttf, *Xtf;
    cudaGetSymbolAddress((void**)&S,    g_S);
    cudaGetSymbolAddress((void**)&S2,   g_S2);
    cudaGetSymbolAddress((void**)&Stf,  g_Stf);
    cudaGetSymbolAddress((void**)&Sntf, g_Sntf);
    cudaGetSymbolAddress((void**)&S2tf, g_S2tf);
    cudaGetSymbolAddress((void**)&Wf,   g_Wf);
    cudaGetSymbolAddress((void**)&Wtf,  g_Wtf);
    cudaGetSymbolAddress((void**)&R1tf, g_R1tf);
    cudaGetSymbolAddress((void**)&R2tf, g_R2tf);
    cudaGetSymbolAddress((void**)&Qttf, g_Qttf);
    cudaGetSymbolAddress((void**)&Xtf,  g_Xtf);

    cudaFuncSetAttribute(tf32_gemm, cudaFuncAttributeMaxDynamicSharedMemorySize, T_SMEM_B);

    build_S_tf<<<NN / 256, 256>>>(Sf, S, Stf, Sntf);
    cvt_tf<<<(BATCHN * Ndim / 4) / 256, 256>>>((const float4*)X, (uint4*)Xtf,
                                               BATCHN * Ndim / 4);

    const int nTriUp  = NT128 * (NT128 + 1) / 2;    // 136
    const int nTriLow = NT128 * (NT128 - 1) / 2;    // 120
    dim3 gSq(NT128, NT128);
    dim3 gMir(16, nTriLow), bMir(32, 8);

    // S2 = S @ S  (upper tiles; D = S @ (-S)^T). out: fp32 + tf32. symmetric.
    tf32_gemm<<<nTriUp, 256, T_SMEM_B>>>(Stf, Sntf,
                                         S2, S2tf,
                                         nullptr, 0.f, nullptr, 0.f, 0.f,
                                         Ndim, Ndim, Ndim, 1);
    mirror_pair<<<gMir, bMir>>>((uint32_t*)S2, S2tf, 0u);

    // W = S2 @ S  (upper tiles). out: fp32 + tf32. antisymmetric.
    tf32_gemm<<<nTriUp, 256, T_SMEM_B>>>(S2tf, Sntf,
                                         (float*)Wf, Wtf,
                                         nullptr, 0.f, nullptr, 0.f, 0.f,
                                         Ndim, Ndim, Ndim, 1);
    mirror_pair<<<gMir, bMir>>>(Wf, Wtf, 0x80000000u);

    // R1^T = C6 I - C7 S + C8 S2 - C9 W
    lincomb_R1t_tf<<<NN / 256, 256>>>(S, S2, (const float*)Wf, R1tf);

    // R2^T = R1^T @ (-W) + C3 I - C4 S + C5 S2    (Bt = W, since (-W)^T = W)
    tf32_gemm<<<gSq, 256, T_SMEM_B>>>(R1tf, Wtf,
                                      nullptr, R2tf,
                                      S, -C4, S2, C5, C3,
                                      Ndim, Ndim, Ndim, 0);
    // Q^T  = R2^T @ (-W) + C0 I - C1 S + C2 S2    -> tf32 directly
    tf32_gemm<<<gSq, 256, T_SMEM_B>>>(R2tf, Wtf,
                                      nullptr, Qttf,
                                      S, -C1, S2, C2, C0,
                                      Ndim, Ndim, Ndim, 0);
    // Y = X @ Q   (Bt = Q^T row-major = Qttf), tf32 single product
    dim3 gY(NT128, BATCHN / 128);
    tf32_gemm<<<gY, 256, T_SMEM_B>>>(Xtf, Qttf,
                                     Y, nullptr,
                                     nullptr, 0.f, nullptr, 0.f, 0.f,
                                     BATCHN, Ndim, Ndim, 0);
}